// round 7
// baseline (speedup 1.0000x reference)
#include <cuda_runtime.h>
#include <cuda_fp16.h>
#include <cstdint>

// Problem constants
#define BB 16
#define NN 16
#define HH 128
#define C2 256
#define NI 128

#define NCHUNK 8             // 4 K-chunks (of 64) x 2 layers
#define WBUF   32768         // weight buffer: 256 rows x 128 B (XOR swizzle, no pad)
#define HBUF   32768         // h tile: 64 rows x 512 B (XOR swizzle, no pad)

// Scratch (device globals: allocation-free contract)
__device__ float g_A   [BB * NI * C2];
__device__ float g_Bvt [BB * C2 * NI];
__device__ float g_part[BB * NI * 2 * C2];
__device__ __align__(16) __half g_Wh[NCHUNK * 256 * 64];  // fp16, chunk-major, k-permuted

__device__ __forceinline__ uint32_t smem_u32(const void* p) {
    return (uint32_t)__cvta_generic_to_shared(p);
}
__device__ __forceinline__ void cpa16(uint32_t dst, const void* src) {
    asm volatile("cp.async.cg.shared.global [%0], [%1], 16;" :: "r"(dst), "l"(src));
}
__device__ __forceinline__ void cpa_commit() { asm volatile("cp.async.commit_group;"); }
__device__ __forceinline__ void cpa_wait0()  { asm volatile("cp.async.wait_group 0;"); }

// fp16-accumulate MMA: D,C are 2 x .f16x2 regs
__device__ __forceinline__ void mma16h(uint32_t* c, const uint32_t* a, const uint32_t* b) {
    asm volatile(
        "mma.sync.aligned.m16n8k16.row.col.f16.f16.f16.f16 "
        "{%0,%1}, {%2,%3,%4,%5}, {%6,%7}, {%0,%1};"
        : "+r"(c[0]), "+r"(c[1])
        : "r"(a[0]), "r"(a[1]), "r"(a[2]), "r"(a[3]), "r"(b[0]), "r"(b[1]));
}

// k-permutation within each 16-group: (2t,2t+1,2t+8,2t+9) -> contiguous (LDS.64 frags)
__device__ __forceinline__ int pg16(int c) {
    return (c & ~15) | ((c & 6) << 1) | ((c & 8) >> 2) | (c & 1);
}

// ---------------------------------------------------------------------------
// k_ab fused: blocks [0,256): layer-1 half projections (8 vectors/block);
//             blocks [256,768): round W2|W3 -> fp16 chunk-major permuted g_Wh.
// ---------------------------------------------------------------------------
__global__ __launch_bounds__(256) void k_ab(const float* __restrict__ enc,
                                            const float* __restrict__ W1,
                                            const float* __restrict__ W2,
                                            const float* __restrict__ W3)
{
    int tid = threadIdx.x;

    if (blockIdx.x >= 256) {
        // ---- weight rounding/permute part ----
        int idx = (blockIdx.x - 256) * 256 + tid;   // 131072
        int L = idx >> 16, rem = idx & 65535;
        int o = rem >> 8, k = rem & 255;
        float v = (L ? W3 : W2)[o * C2 + k];
        int ck = (L << 2) | (k >> 6);
        int k6 = k & 63;
        int k4 = k6 & 15;
        int pk = (k6 & 48) | ((k4 & 6) << 1) | ((k4 & 8) >> 2) | (k4 & 1);
        g_Wh[ck * 16384 + o * 64 + pk] = __float2half_rn(v);
        return;
    }

    __shared__ float e_s[8 * HH];       // 4 KB
    __shared__ float w_s[C2 * 36];      // 36 KB, float4-aligned rows, 4tid banks/phase
    int vb = blockIdx.x * 8;

    ((float4*)e_s)[tid] = ((const float4*)(enc + vb * HH))[tid];

    float acc[2][8];
#pragma unroll
    for (int hf = 0; hf < 2; hf++)
#pragma unroll
        for (int v = 0; v < 8; v++) acc[hf][v] = 0.f;

    for (int kt = 0; kt < C2; kt += 32) {
        __syncthreads();
#pragma unroll
        for (int r = 0; r < 8; r++) {
            int idx = tid + r * 256;
            int o = idx >> 3, c4 = idx & 7;
            *(float4*)&w_s[o * 36 + c4 * 4] = *(const float4*)(W1 + o * C2 + kt + c4 * 4);
        }
        __syncthreads();
        int hf = kt >> 7, kb = kt & 127;
#pragma unroll
        for (int k4 = 0; k4 < 8; k4++) {
            float4 w4 = *(const float4*)&w_s[tid * 36 + k4 * 4];
#pragma unroll
            for (int v = 0; v < 8; v++) {
                float4 e4 = *(const float4*)&e_s[v * HH + kb + k4 * 4];
                acc[hf][v] = fmaf(w4.x, e4.x,
                             fmaf(w4.y, e4.y,
                             fmaf(w4.z, e4.z,
                             fmaf(w4.w, e4.w, acc[hf][v]))));
            }
        }
    }
    int b = vb >> 7, i0 = vb & 127;
#pragma unroll
    for (int v = 0; v < 8; v++) {
        g_A  [(vb + v) * C2 + tid]          = acc[0][v];
        g_Bvt[(b * C2 + tid) * NI + i0 + v] = acc[1][v];
    }
}

// ---------------------------------------------------------------------------
// k_main: fused 2-layer GEMM, fp16-ACCUM m16n8k16, 2 CTAs/SM.
// CTA = (b, i, jhalf): M=64 rows x 256 cols, K=256, two layers.
// In-flight f16 accumulation limited to one K=64 chunk (acch), folded into a
// running f16x2 total (accf) via HADD2 each chunk. Row-sum/mean in fp32.
// ---------------------------------------------------------------------------
__global__ __launch_bounds__(256, 2) void k_main()
{
    extern __shared__ char smem[];
    char* hb = smem;                       // h tile, 32 KB
    char* wbase = smem + HBUF;             // 2 weight buffers, 64 KB
    uint32_t w_u32 = smem_u32(wbase);

    int tid  = threadIdx.x;
    int lane = tid & 31;
    int wid  = tid >> 5;
    int wy   = wid & 1;
    int wx   = wid >> 1;
    int mrow = wy * 32;
    int ncol = wx * 64;

    int blk = blockIdx.x;
    int b   = blk >> 8;
    int rem = blk & 255;
    int i   = rem >> 1;
    int jh  = rem & 1;
    int j0  = jh * 64;

    // ---- prefetch chunk 0 ----
#pragma unroll
    for (int r = 0; r < 8; r++) {
        int idx = tid + r * 256;
        int o = idx >> 3, c4 = idx & 7;
        uint32_t inner = (uint32_t)((c4 * 16) ^ ((o & 3) << 5));
        cpa16(w_u32 + (uint32_t)o * 128 + inner, g_Wh + o * 64 + c4 * 8);
    }
    cpa_commit();

    // ---- build h1 while chunk 0 flies ----
    {
        int p   = tid & 127;
        int rg  = tid >> 7;
        int c0  = 2 * p;
        float a0 = g_A[(b * NI + i) * C2 + c0];
        float a1 = g_A[(b * NI + i) * C2 + c0 + 1];
        const float* bp0 = g_Bvt + (b * C2 + c0)     * NI + j0 + rg * 32;
        const float* bp1 = g_Bvt + (b * C2 + c0 + 1) * NI + j0 + rg * 32;
        int pcb = pg16(c0) * 2;
#pragma unroll
        for (int r4 = 0; r4 < 32; r4 += 4) {
            float4 v0 = *(const float4*)(bp0 + r4);
            float4 v1 = *(const float4*)(bp1 + r4);
            int row = rg * 32 + r4;
#pragma unroll
            for (int q = 0; q < 4; q++) {
                float e0 = (q == 0 ? v0.x : q == 1 ? v0.y : q == 2 ? v0.z : v0.w);
                float e1 = (q == 0 ? v1.x : q == 1 ? v1.y : q == 2 ? v1.z : v1.w);
                __half2 hv = __floats2half2_rn(fmaxf(e0 + a0, 0.f), fmaxf(e1 + a1, 0.f));
                int rr = row + q;
                *(__half2*)(hb + rr * 512 + (pcb ^ ((rr & 3) << 5))) = hv;
            }
        }
    }

    uint32_t accf[2][8][2];                // running totals, f16x2
#pragma unroll
    for (int mt = 0; mt < 2; mt++)
#pragma unroll
        for (int nt = 0; nt < 8; nt++)
            accf[mt][nt][0] = accf[mt][nt][1] = 0u;

    for (int ck = 0; ck < NCHUNK; ck++) {
        cpa_wait0();
        __syncthreads();

        if (ck < NCHUNK - 1) {
            const __half* src = g_Wh + (ck + 1) * 16384;
            uint32_t dbase = w_u32 + (uint32_t)(((ck + 1) & 1) * WBUF);
#pragma unroll
            for (int r = 0; r < 8; r++) {
                int idx = tid + r * 256;
                int o = idx >> 3, c4 = idx & 7;
                uint32_t inner = (uint32_t)((c4 * 16) ^ ((o & 3) << 5));
                cpa16(dbase + (uint32_t)o * 128 + inner, src + o * 64 + c4 * 8);
            }
            cpa_commit();
        }

        // ---- compute chunk ck (K=64 in-flight f16 accum) ----
        uint32_t acch[2][8][2];
#pragma unroll
        for (int mt = 0; mt < 2; mt++)
#pragma unroll
            for (int nt = 0; nt < 8; nt++)
                acch[mt][nt][0] = acch[mt][nt][1] = 0u;

        char* wc  = wbase + (ck & 1) * WBUF;
        int   ckb = (ck & 3) * 128;
#pragma unroll
        for (int ks = 0; ks < 4; ks++) {
            uint32_t a[2][4];
#pragma unroll
            for (int mt = 0; mt < 2; mt++) {
                int r0 = mrow + mt * 16 + (lane >> 2);
                uint32_t inner = (uint32_t)((ckb + ks * 32 + (lane & 3) * 8));
                uint2 lo = *(const uint2*)(hb + r0 * 512 + (inner ^ ((r0 & 3) << 5)));
                int r8 = r0 + 8;
                uint2 hi = *(const uint2*)(hb + r8 * 512 + (inner ^ ((r8 & 3) << 5)));
                a[mt][0] = lo.x; a[mt][2] = lo.y;
                a[mt][1] = hi.x; a[mt][3] = hi.y;
            }
#pragma unroll
            for (int nt = 0; nt < 8; nt++) {
                int o = ncol + nt * 8 + (lane >> 2);
                uint32_t inner = (uint32_t)((ks * 32 + (lane & 3) * 8) ^ ((o & 3) << 5));
                uint2 bv = *(const uint2*)(wc + o * 128 + inner);
                uint32_t bfr[2] = {bv.x, bv.y};
                mma16h(acch[0][nt], a[0], bfr);
                mma16h(acch[1][nt], a[1], bfr);
            }
        }

        // ---- fold chunk into running f16x2 totals ----
#pragma unroll
        for (int mt = 0; mt < 2; mt++)
#pragma unroll
            for (int nt = 0; nt < 8; nt++) {
                *(__half2*)&accf[mt][nt][0] =
                    __hadd2(*(__half2*)&accf[mt][nt][0], *(__half2*)&acch[mt][nt][0]);
                *(__half2*)&accf[mt][nt][1] =
                    __hadd2(*(__half2*)&accf[mt][nt][1], *(__half2*)&acch[mt][nt][1]);
            }

        if (ck == 3) {
            // layer boundary: h2 = relu(accf), same permuted+swizzled layout
            __syncthreads();
            const __half2 z2 = __floats2half2_rn(0.f, 0.f);
#pragma unroll
            for (int mt = 0; mt < 2; mt++) {
                int r = mrow + mt * 16 + (lane >> 2);
#pragma unroll
                for (int nt = 0; nt < 8; nt++) {
                    int c0 = ncol + nt * 8 + 2 * (lane & 3);
                    int pcb = pg16(c0) * 2;
                    __half2 v01 = __hmax2(*(__half2*)&accf[mt][nt][0], z2);
                    __half2 v23 = __hmax2(*(__half2*)&accf[mt][nt][1], z2);
                    int r8 = r + 8;
                    *(__half2*)(hb + r * 512 + (pcb ^ ((r & 3) << 5)))   = v01;
                    *(__half2*)(hb + r8 * 512 + (pcb ^ ((r8 & 3) << 5))) = v23;
                    accf[mt][nt][0] = accf[mt][nt][1] = 0u;
                }
            }
            // next iteration's top __syncthreads orders writes before reads
        }
    }

    // ---- epilogue: relu + deterministic fp32 sum over the CTA's 64 rows ----
    __syncthreads();
    float* red = (float*)wbase;            // [2][256]
#pragma unroll
    for (int nt = 0; nt < 8; nt++) {
        float ev = 0.f, od = 0.f;
#pragma unroll
        for (int mt = 0; mt < 2; mt++) {
            float2 lo = __half22float2(*(__half2*)&accf[mt][nt][0]);
            float2 hi = __half22float2(*(__half2*)&accf[mt][nt][1]);
            ev += fmaxf(lo.x, 0.f) + fmaxf(hi.x, 0.f);
            od += fmaxf(lo.y, 0.f) + fmaxf(hi.y, 0.f);
        }
#pragma unroll
        for (int o = 4; o <= 16; o <<= 1) {
            ev += __shfl_xor_sync(0xffffffffu, ev, o);
            od += __shfl_xor_sync(0xffffffffu, od, o);
        }
        if (lane < 4) {
            red[wy * C2 + ncol + nt * 8 + 2 * lane]     = ev;
            red[wy * C2 + ncol + nt * 8 + 2 * lane + 1] = od;
        }
    }
    __syncthreads();
    g_part[((b * NI + i) * 2 + jh) * C2 + tid] = red[tid] + red[C2 + tid];
}

// ---------------------------------------------------------------------------
__global__ void k_fin(float* __restrict__ out)
{
    int idx = blockIdx.x * 256 + threadIdx.x;
    int c = idx & 255, bn = idx >> 8;
    int b = bn >> 4, n1 = bn & 15;
    float sum = 0.f;
#pragma unroll
    for (int k1 = 0; k1 < 8; k1++)
#pragma unroll
        for (int jhv = 0; jhv < 2; jhv++)
            sum += g_part[((b * NI + n1 * 8 + k1) * 2 + jhv) * C2 + c];
    out[idx] = sum * (1.0f / 1024.0f);
}

// ---------------------------------------------------------------------------
extern "C" void kernel_launch(void* const* d_in, const int* in_sizes, int n_in,
                              void* d_out, int out_size)
{
    const float* enc = (const float*)d_in[0];
    const float* W1  = (const float*)d_in[1];
    const float* W2  = (const float*)d_in[2];
    const float* W3  = (const float*)d_in[3];
    float* out       = (float*)d_out;

    const int smem_bytes = HBUF + 2 * WBUF;   // 98304
    cudaFuncSetAttribute(k_main, cudaFuncAttributeMaxDynamicSharedMemorySize, smem_bytes);

    k_ab  <<<768, 256>>>(enc, W1, W2, W3);
    k_main<<<BB * NI * 2, 256, smem_bytes>>>();
    k_fin <<<(BB * NN * C2) / 256, 256>>>(out);
}

// round 8
// speedup vs baseline: 1.0753x; 1.0753x over previous
#include <cuda_runtime.h>
#include <cuda_fp16.h>
#include <cstdint>

// Problem constants
#define BB 16
#define NN 16
#define HH 128
#define C2 256
#define NI 128

#define NCHUNK 8             // 4 K-chunks (of 64) x 2 layers
#define WBUF   32768         // weight buffer: 256 rows x 128 B (XOR swizzle, no pad)
#define HBUF   32768         // h tile: 64 rows x 512 B (XOR swizzle, no pad)

// Scratch (device globals: allocation-free contract)
__device__ float g_A   [BB * NI * C2];
__device__ float g_Bvt [BB * C2 * NI];
__device__ float g_part[BB * NI * 2 * C2];
__device__ __align__(16) __half g_Wh [NCHUNK * 256 * 64]; // W2|W3 fp16, chunk-major, k-perm
__device__ __align__(16) __half g_W1h[512 * 128];         // [W1L|W1R] fp16, k-perm
__device__ __align__(16) __half g_ench[BB * NI * HH];     // enc fp16, k-perm

__device__ __forceinline__ uint32_t smem_u32(const void* p) {
    return (uint32_t)__cvta_generic_to_shared(p);
}
__device__ __forceinline__ void cpa16(uint32_t dst, const void* src) {
    asm volatile("cp.async.cg.shared.global [%0], [%1], 16;" :: "r"(dst), "l"(src));
}
__device__ __forceinline__ void cpa_commit() { asm volatile("cp.async.commit_group;"); }
__device__ __forceinline__ void cpa_wait0()  { asm volatile("cp.async.wait_group 0;"); }

__device__ __forceinline__ void mma16(float* c, const uint32_t* a, const uint32_t* b) {
    asm volatile(
        "mma.sync.aligned.m16n8k16.row.col.f32.f16.f16.f32 "
        "{%0,%1,%2,%3}, {%4,%5,%6,%7}, {%8,%9}, {%0,%1,%2,%3};"
        : "+f"(c[0]), "+f"(c[1]), "+f"(c[2]), "+f"(c[3])
        : "r"(a[0]), "r"(a[1]), "r"(a[2]), "r"(a[3]), "r"(b[0]), "r"(b[1]));
}

// k-permutation within each 16-group: (2t,2t+1,2t+8,2t+9) -> contiguous (LDS.64 frags)
__device__ __forceinline__ int pg16(int c) {
    return (c & ~15) | ((c & 6) << 1) | ((c & 8) >> 2) | (c & 1);
}

// ---------------------------------------------------------------------------
// k_prep: all fp16 conversions/packings.
//  blocks [0,512):    W2|W3 -> g_Wh   (chunk-major, k-permuted)
//  blocks [512,768):  [W1L|W1R] -> g_W1h[n][k], n in [0,512), k in [0,128)
//  blocks [768,1792): enc -> g_ench (k-permuted)
// ---------------------------------------------------------------------------
__global__ __launch_bounds__(256) void k_prep(const float* __restrict__ enc,
                                              const float* __restrict__ W1,
                                              const float* __restrict__ W2,
                                              const float* __restrict__ W3)
{
    int tid = threadIdx.x;
    int blk = blockIdx.x;

    if (blk < 512) {
        int idx = blk * 256 + tid;                  // 131072
        int L = idx >> 16, rem = idx & 65535;
        int o = rem >> 8, k = rem & 255;
        float v = (L ? W3 : W2)[o * C2 + k];
        int ck = (L << 2) | (k >> 6);
        int k6 = k & 63;
        int pk = (k6 & 48) | pg16(k6 & 15);
        g_Wh[ck * 16384 + o * 64 + pk] = __float2half_rn(v);
    } else if (blk < 768) {
        int idx = (blk - 512) * 256 + tid;          // 65536
        int n = idx >> 7, k = idx & 127;            // n in [0,512), k in [0,128)
        float v = (n < 256) ? W1[n * C2 + k] : W1[(n - 256) * C2 + 128 + k];
        g_W1h[n * 128 + pg16(k)] = __float2half_rn(v);
    } else {
        int idx = (blk - 768) * 256 + tid;          // 262144
        int v = idx >> 7, k = idx & 127;
        g_ench[v * 128 + pg16(k)] = __float2half_rn(enc[v * HH + k]);
    }
}

// ---------------------------------------------------------------------------
// k_abt: layer-1 half projections on tensor cores.
// out[v][n] (n<256: A, n>=256: Bv) = enc[v] @ Wab[n]^T, K=128, fp32 accum.
// CTA = 32 vectors x 512 outputs; 64 CTAs, 256 threads (8 warps, tile 32x64).
// smem: enc tile 32x256B + W 512x256B = 136 KB (XOR-swizzled, same as k_main).
// ---------------------------------------------------------------------------
__global__ __launch_bounds__(256, 1) void k_abt()
{
    extern __shared__ char smem[];
    char* es = smem;                 // 8 KB enc tile
    char* wsm = smem + 8192;         // 128 KB weights
    uint32_t es_u = smem_u32(es), ws_u = smem_u32(wsm);

    int tid  = threadIdx.x;
    int lane = tid & 31;
    int wid  = tid >> 5;
    int vb   = blockIdx.x * 32;
    int b    = vb >> 7;

    // enc tile: 512 x 16B chunks -> 2 per thread
#pragma unroll
    for (int r = 0; r < 2; r++) {
        int idx = tid + r * 256;
        int v = idx >> 4, c4 = idx & 15;
        uint32_t inner = (uint32_t)((c4 * 16) ^ ((v & 3) << 5));
        cpa16(es_u + (uint32_t)v * 256 + inner, g_ench + (vb + v) * 128 + c4 * 8);
    }
    // W tile: 8192 x 16B chunks -> 32 per thread
#pragma unroll
    for (int r = 0; r < 32; r++) {
        int idx = tid + r * 256;
        int o = idx >> 4, c4 = idx & 15;
        uint32_t inner = (uint32_t)((c4 * 16) ^ ((o & 3) << 5));
        cpa16(ws_u + (uint32_t)o * 256 + inner, g_W1h + o * 128 + c4 * 8);
    }
    cpa_commit();
    cpa_wait0();
    __syncthreads();

    float acc[2][8][4];
#pragma unroll
    for (int mt = 0; mt < 2; mt++)
#pragma unroll
        for (int nt = 0; nt < 8; nt++)
#pragma unroll
            for (int q = 0; q < 4; q++) acc[mt][nt][q] = 0.f;

#pragma unroll
    for (int ks = 0; ks < 8; ks++) {
        uint32_t a[2][4];
#pragma unroll
        for (int mt = 0; mt < 2; mt++) {
            int r0 = mt * 16 + (lane >> 2);
            uint32_t inner = (uint32_t)(ks * 32 + (lane & 3) * 8);
            uint2 lo = *(const uint2*)(es + r0 * 256 + (inner ^ ((r0 & 3) << 5)));
            int r8 = r0 + 8;
            uint2 hi = *(const uint2*)(es + r8 * 256 + (inner ^ ((r8 & 3) << 5)));
            a[mt][0] = lo.x; a[mt][2] = lo.y;
            a[mt][1] = hi.x; a[mt][3] = hi.y;
        }
#pragma unroll
        for (int nt = 0; nt < 8; nt++) {
            int o = wid * 64 + nt * 8 + (lane >> 2);
            uint32_t inner = (uint32_t)((ks * 32 + (lane & 3) * 8) ^ ((o & 3) << 5));
            uint2 bv = *(const uint2*)(wsm + o * 256 + inner);
            uint32_t bfr[2] = {bv.x, bv.y};
            mma16(acc[0][nt], a[0], bfr);
            mma16(acc[1][nt], a[1], bfr);
        }
    }

    // write out: n<256 -> g_A[v][n]; n>=256 -> g_Bvt[b][n-256][v&127]
#pragma unroll
    for (int mt = 0; mt < 2; mt++) {
        int v0 = vb + mt * 16 + (lane >> 2);
#pragma unroll
        for (int nt = 0; nt < 8; nt++) {
            int n0 = wid * 64 + nt * 8 + 2 * (lane & 3);
#pragma unroll
            for (int q = 0; q < 4; q++) {
                int v = v0 + (q >= 2 ? 8 : 0);
                int n = n0 + (q & 1);
                float x = acc[mt][nt][q];
                if (n < 256) g_A[v * C2 + n] = x;
                else         g_Bvt[(b * C2 + (n - 256)) * NI + (v & 127)] = x;
            }
        }
    }
}

// ---------------------------------------------------------------------------
// k_main: fused 2-layer GEMM, fp16 m16n8k16 (fp32 accum), 2 CTAs/SM.
// (Round-6 champion, unchanged.)
// ---------------------------------------------------------------------------
__global__ __launch_bounds__(256, 2) void k_main()
{
    extern __shared__ char smem[];
    char* hb = smem;                       // h tile, 32 KB
    char* wbase = smem + HBUF;             // 2 weight buffers, 64 KB
    uint32_t w_u32 = smem_u32(wbase);

    int tid  = threadIdx.x;
    int lane = tid & 31;
    int wid  = tid >> 5;
    int wy   = wid & 1;
    int wx   = wid >> 1;
    int mrow = wy * 32;
    int ncol = wx * 64;

    int blk = blockIdx.x;
    int b   = blk >> 8;
    int rem = blk & 255;
    int i   = rem >> 1;
    int jh  = rem & 1;
    int j0  = jh * 64;

    // ---- prefetch chunk 0 ----
#pragma unroll
    for (int r = 0; r < 8; r++) {
        int idx = tid + r * 256;
        int o = idx >> 3, c4 = idx & 7;
        uint32_t inner = (uint32_t)((c4 * 16) ^ ((o & 3) << 5));
        cpa16(w_u32 + (uint32_t)o * 128 + inner, g_Wh + o * 64 + c4 * 8);
    }
    cpa_commit();

    // ---- build h1 while chunk 0 flies ----
    {
        int p   = tid & 127;
        int rg  = tid >> 7;
        int c0  = 2 * p;
        float a0 = g_A[(b * NI + i) * C2 + c0];
        float a1 = g_A[(b * NI + i) * C2 + c0 + 1];
        const float* bp0 = g_Bvt + (b * C2 + c0)     * NI + j0 + rg * 32;
        const float* bp1 = g_Bvt + (b * C2 + c0 + 1) * NI + j0 + rg * 32;
        int pcb = pg16(c0) * 2;
#pragma unroll
        for (int r4 = 0; r4 < 32; r4 += 4) {
            float4 v0 = *(const float4*)(bp0 + r4);
            float4 v1 = *(const float4*)(bp1 + r4);
            int row = rg * 32 + r4;
#pragma unroll
            for (int q = 0; q < 4; q++) {
                float e0 = (q == 0 ? v0.x : q == 1 ? v0.y : q == 2 ? v0.z : v0.w);
                float e1 = (q == 0 ? v1.x : q == 1 ? v1.y : q == 2 ? v1.z : v1.w);
                __half2 hv = __floats2half2_rn(fmaxf(e0 + a0, 0.f), fmaxf(e1 + a1, 0.f));
                int rr = row + q;
                *(__half2*)(hb + rr * 512 + (pcb ^ ((rr & 3) << 5))) = hv;
            }
        }
    }

    float acc[2][8][4];
#pragma unroll
    for (int mt = 0; mt < 2; mt++)
#pragma unroll
        for (int nt = 0; nt < 8; nt++)
#pragma unroll
            for (int q = 0; q < 4; q++) acc[mt][nt][q] = 0.f;

    for (int ck = 0; ck < NCHUNK; ck++) {
        cpa_wait0();
        __syncthreads();

        if (ck < NCHUNK - 1) {             // prefetch ck+1 into the other buffer
            const __half* src = g_Wh + (ck + 1) * 16384;
            uint32_t dbase = w_u32 + (uint32_t)(((ck + 1) & 1) * WBUF);
#pragma unroll
            for (int r = 0; r < 8; r++) {
                int idx = tid + r * 256;
                int o = idx >> 3, c4 = idx & 7;
                uint32_t inner = (uint32_t)((c4 * 16) ^ ((o & 3) << 5));
                cpa16(dbase + (uint32_t)o * 128 + inner, src + o * 64 + c4 * 8);
            }
            cpa_commit();
        }

        // ---- compute chunk ck (K=64 -> 4 ksteps of 16) ----
        char* wc  = wbase + (ck & 1) * WBUF;
        int   ckb = (ck & 3) * 128;
#pragma unroll
        for (int ks = 0; ks < 4; ks++) {
            uint32_t a[2][4];
#pragma unroll
            for (int mt = 0; mt < 2; mt++) {
                int r0 = mrow + mt * 16 + (lane >> 2);
                uint32_t inner = (uint32_t)((ckb + ks * 32 + (lane & 3) * 8));
                uint2 lo = *(const uint2*)(hb + r0 * 512 + (inner ^ ((r0 & 3) << 5)));
                int r8 = r0 + 8;
                uint2 hi = *(const uint2*)(hb + r8 * 512 + (inner ^ ((r8 & 3) << 5)));
                a[mt][0] = lo.x; a[mt][2] = lo.y;
                a[mt][1] = hi.x; a[mt][3] = hi.y;
            }
#pragma unroll
            for (int nt = 0; nt < 8; nt++) {
                int o = ncol + nt * 8 + (lane >> 2);
                uint32_t inner = (uint32_t)((ks * 32 + (lane & 3) * 8) ^ ((o & 3) << 5));
                uint2 bv = *(const uint2*)(wc + o * 128 + inner);
                uint32_t bfr[2] = {bv.x, bv.y};
                mma16(acc[0][nt], a[0], bfr);
                mma16(acc[1][nt], a[1], bfr);
            }
        }

        if (ck == 3) {
            // layer boundary: overwrite h with h2 (same permuted+swizzled layout)
            __syncthreads();
#pragma unroll
            for (int mt = 0; mt < 2; mt++) {
                int r = mrow + mt * 16 + (lane >> 2);
#pragma unroll
                for (int nt = 0; nt < 8; nt++) {
                    int c0 = ncol + nt * 8 + 2 * (lane & 3);
                    int pcb = pg16(c0) * 2;
                    __half2 v01 = __floats2half2_rn(fmaxf(acc[mt][nt][0], 0.f),
                                                    fmaxf(acc[mt][nt][1], 0.f));
                    __half2 v23 = __floats2half2_rn(fmaxf(acc[mt][nt][2], 0.f),
                                                    fmaxf(acc[mt][nt][3], 0.f));
                    int r8 = r + 8;
                    *(__half2*)(hb + r * 512 + (pcb ^ ((r & 3) << 5)))   = v01;
                    *(__half2*)(hb + r8 * 512 + (pcb ^ ((r8 & 3) << 5))) = v23;
#pragma unroll
                    for (int q = 0; q < 4; q++) acc[mt][nt][q] = 0.f;
                }
            }
        }
    }

    // ---- epilogue: relu + deterministic sum over the CTA's 64 rows ----
    __syncthreads();
    float* red = (float*)wbase;            // [2][256]
#pragma unroll
    for (int nt = 0; nt < 8; nt++) {
        float ev = 0.f, od = 0.f;
#pragma unroll
        for (int mt = 0; mt < 2; mt++) {
            ev += fmaxf(acc[mt][nt][0], 0.f) + fmaxf(acc[mt][nt][2], 0.f);
            od += fmaxf(acc[mt][nt][1], 0.f) + fmaxf(acc[mt][nt][3], 0.f);
        }
#pragma unroll
        for (int o = 4; o <= 16; o <<= 1) {
            ev += __shfl_xor_sync(0xffffffffu, ev, o);
            od += __shfl_xor_sync(0xffffffffu, od, o);
        }
        if (lane < 4) {
            red[wy * C2 + ncol + nt * 8 + 2 * lane]     = ev;
            red[wy * C2 + ncol + nt * 8 + 2 * lane + 1] = od;
        }
    }
    __syncthreads();
    g_part[((b * NI + i) * 2 + jh) * C2 + tid] = red[tid] + red[C2 + tid];
}

// ---------------------------------------------------------------------------
__global__ void k_fin(float* __restrict__ out)
{
    int idx = blockIdx.x * 256 + threadIdx.x;
    int c = idx & 255, bn = idx >> 8;
    int b = bn >> 4, n1 = bn & 15;
    float sum = 0.f;
#pragma unroll
    for (int k1 = 0; k1 < 8; k1++)
#pragma unroll
        for (int jhv = 0; jhv < 2; jhv++)
            sum += g_part[((b * NI + n1 * 8 + k1) * 2 + jhv) * C2 + c];
    out[idx] = sum * (1.0f / 1024.0f);
}

// ---------------------------------------------------------------------------
extern "C" void kernel_launch(void* const* d_in, const int* in_sizes, int n_in,
                              void* d_out, int out_size)
{
    const float* enc = (const float*)d_in[0];
    const float* W1  = (const float*)d_in[1];
    const float* W2  = (const float*)d_in[2];
    const float* W3  = (const float*)d_in[3];
    float* out       = (float*)d_out;

    const int smem_main = HBUF + 2 * WBUF;   // 98304
    const int smem_abt  = 8192 + 512 * 256;  // 139264
    cudaFuncSetAttribute(k_main, cudaFuncAttributeMaxDynamicSharedMemorySize, smem_main);
    cudaFuncSetAttribute(k_abt,  cudaFuncAttributeMaxDynamicSharedMemorySize, smem_abt);

    k_prep<<<1792, 256>>>(enc, W1, W2, W3);
    k_abt <<<BB * NI / 32, 256, smem_abt>>>();
    k_main<<<BB * NI * 2, 256, smem_main>>>();
    k_fin <<<(BB * NN * C2) / 256, 256>>>(out);
}

// round 9
// speedup vs baseline: 1.0811x; 1.0054x over previous
#include <cuda_runtime.h>
#include <cuda_fp16.h>
#include <cstdint>

// Problem constants
#define BB 16
#define NN 16
#define HH 128
#define C2 256
#define NI 128

#define NCHUNK 8             // 4 K-chunks (of 64) x 2 layers
#define WBUF   32768         // weight buffer: 256 rows x 128 B (XOR swizzle, no pad)
#define HBUF   32768         // h tile: 64 rows x 512 B (XOR swizzle, no pad)

// Scratch (device globals: allocation-free contract)
__device__ float g_A   [BB * NI * C2];
__device__ float g_Bvt [BB * C2 * NI];
__device__ float g_part[BB * NI * 2 * C2];
__device__ __align__(16) __half g_Wh [NCHUNK * 256 * 64]; // W2|W3 fp16, chunk-major, k-perm
__device__ __align__(16) __half g_W1h[512 * 128];         // [W1L|W1R] fp16, k-perm
__device__ __align__(16) __half g_ench[BB * NI * HH];     // enc fp16, k-perm

__device__ __forceinline__ uint32_t smem_u32(const void* p) {
    return (uint32_t)__cvta_generic_to_shared(p);
}
__device__ __forceinline__ void cpa16(uint32_t dst, const void* src) {
    asm volatile("cp.async.cg.shared.global [%0], [%1], 16;" :: "r"(dst), "l"(src));
}
__device__ __forceinline__ void cpa_commit() { asm volatile("cp.async.commit_group;"); }
__device__ __forceinline__ void cpa_wait0()  { asm volatile("cp.async.wait_group 0;"); }

__device__ __forceinline__ void mma16(float* c, const uint32_t* a, const uint32_t* b) {
    asm volatile(
        "mma.sync.aligned.m16n8k16.row.col.f32.f16.f16.f32 "
        "{%0,%1,%2,%3}, {%4,%5,%6,%7}, {%8,%9}, {%0,%1,%2,%3};"
        : "+f"(c[0]), "+f"(c[1]), "+f"(c[2]), "+f"(c[3])
        : "r"(a[0]), "r"(a[1]), "r"(a[2]), "r"(a[3]), "r"(b[0]), "r"(b[1]));
}

// k-permutation within each 16-group: (2t,2t+1,2t+8,2t+9) -> contiguous (LDS.64 frags)
__device__ __forceinline__ int pg16(int c) {
    return (c & ~15) | ((c & 6) << 1) | ((c & 8) >> 2) | (c & 1);
}

// ---------------------------------------------------------------------------
// k_prep: all fp16 conversions/packings, 2 elems/thread (896 blocks).
//  blocks [0,256):    W2|W3 -> g_Wh   (chunk-major, k-permuted)
//  blocks [256,384):  [W1L|W1R] -> g_W1h[n][k]
//  blocks [384,896):  enc -> g_ench (k-permuted)
// ---------------------------------------------------------------------------
__global__ __launch_bounds__(256) void k_prep(const float* __restrict__ enc,
                                              const float* __restrict__ W1,
                                              const float* __restrict__ W2,
                                              const float* __restrict__ W3)
{
    int tid = threadIdx.x;
    int blk = blockIdx.x;

    if (blk < 256) {
        int base = blk * 512 + tid * 2;              // 2 consecutive k per thread
#pragma unroll
        for (int e = 0; e < 2; e++) {
            int idx = base + e;                      // 131072 total
            int L = idx >> 16, rem = idx & 65535;
            int o = rem >> 8, k = rem & 255;
            float v = (L ? W3 : W2)[o * C2 + k];
            int ck = (L << 2) | (k >> 6);
            int k6 = k & 63;
            int pk = (k6 & 48) | pg16(k6 & 15);
            g_Wh[ck * 16384 + o * 64 + pk] = __float2half_rn(v);
        }
    } else if (blk < 384) {
        int base = (blk - 256) * 512 + tid * 2;      // 65536 total
#pragma unroll
        for (int e = 0; e < 2; e++) {
            int idx = base + e;
            int n = idx >> 7, k = idx & 127;
            float v = (n < 256) ? W1[n * C2 + k] : W1[(n - 256) * C2 + 128 + k];
            g_W1h[n * 128 + pg16(k)] = __float2half_rn(v);
        }
    } else {
        int base = (blk - 384) * 512 + tid * 2;      // 262144 total
#pragma unroll
        for (int e = 0; e < 2; e++) {
            int idx = base + e;
            int v = idx >> 7, k = idx & 127;
            g_ench[v * 128 + pg16(k)] = __float2half_rn(enc[v * HH + k]);
        }
    }
}

// ---------------------------------------------------------------------------
// k_abt: layer-1 half projections on tensor cores, full-chip width.
// CTA = 16 vectors x 512 outputs; 128 CTAs, 256 threads (8 warps, tile 16x64).
// smem: enc tile 16x256B (4 KB) + W 512x256B (128 KB), XOR-swizzled.
// ---------------------------------------------------------------------------
__global__ __launch_bounds__(256, 1) void k_abt()
{
    extern __shared__ char smem[];
    char* es = smem;                 // 4 KB enc tile
    char* wsm = smem + 4096;         // 128 KB weights
    uint32_t es_u = smem_u32(es), ws_u = smem_u32(wsm);

    int tid  = threadIdx.x;
    int lane = tid & 31;
    int wid  = tid >> 5;
    int vb   = blockIdx.x * 16;
    int b    = vb >> 7;

    // enc tile: 256 x 16B chunks -> 1 per thread
    {
        int v = tid >> 4, c4 = tid & 15;
        uint32_t inner = (uint32_t)((c4 * 16) ^ ((v & 3) << 5));
        cpa16(es_u + (uint32_t)v * 256 + inner, g_ench + (vb + v) * 128 + c4 * 8);
    }
    // W tile: 8192 x 16B chunks -> 32 per thread
#pragma unroll
    for (int r = 0; r < 32; r++) {
        int idx = tid + r * 256;
        int o = idx >> 4, c4 = idx & 15;
        uint32_t inner = (uint32_t)((c4 * 16) ^ ((o & 3) << 5));
        cpa16(ws_u + (uint32_t)o * 256 + inner, g_W1h + o * 128 + c4 * 8);
    }
    cpa_commit();
    cpa_wait0();
    __syncthreads();

    float acc[8][4];
#pragma unroll
    for (int nt = 0; nt < 8; nt++)
#pragma unroll
        for (int q = 0; q < 4; q++) acc[nt][q] = 0.f;

#pragma unroll
    for (int ks = 0; ks < 8; ks++) {
        uint32_t a[4];
        {
            int r0 = lane >> 2;
            uint32_t inner = (uint32_t)(ks * 32 + (lane & 3) * 8);
            uint2 lo = *(const uint2*)(es + r0 * 256 + (inner ^ ((r0 & 3) << 5)));
            int r8 = r0 + 8;
            uint2 hi = *(const uint2*)(es + r8 * 256 + (inner ^ ((r8 & 3) << 5)));
            a[0] = lo.x; a[2] = lo.y;
            a[1] = hi.x; a[3] = hi.y;
        }
#pragma unroll
        for (int nt = 0; nt < 8; nt++) {
            int o = wid * 64 + nt * 8 + (lane >> 2);
            uint32_t inner = (uint32_t)((ks * 32 + (lane & 3) * 8) ^ ((o & 3) << 5));
            uint2 bv = *(const uint2*)(wsm + o * 256 + inner);
            uint32_t bfr[2] = {bv.x, bv.y};
            mma16(acc[nt], a, bfr);
        }
    }

    // write out: n<256 -> g_A[v][n]; n>=256 -> g_Bvt[b][n-256][v&127]
    {
        int v0 = vb + (lane >> 2);
#pragma unroll
        for (int nt = 0; nt < 8; nt++) {
            int n0 = wid * 64 + nt * 8 + 2 * (lane & 3);
#pragma unroll
            for (int q = 0; q < 4; q++) {
                int v = v0 + (q >= 2 ? 8 : 0);
                int n = n0 + (q & 1);
                float x = acc[nt][q];
                if (n < 256) g_A[v * C2 + n] = x;
                else         g_Bvt[(b * C2 + (n - 256)) * NI + (v & 127)] = x;
            }
        }
    }
}

// ---------------------------------------------------------------------------
// k_main: fused 2-layer GEMM, fp16 m16n8k16 (fp32 accum), 2 CTAs/SM.
// AT the legacy-tensor HW floor (512 MAC/cyc/SM) — unchanged champion.
// ---------------------------------------------------------------------------
__global__ __launch_bounds__(256, 2) void k_main()
{
    extern __shared__ char smem[];
    char* hb = smem;                       // h tile, 32 KB
    char* wbase = smem + HBUF;             // 2 weight buffers, 64 KB
    uint32_t w_u32 = smem_u32(wbase);

    int tid  = threadIdx.x;
    int lane = tid & 31;
    int wid  = tid >> 5;
    int wy   = wid & 1;
    int wx   = wid >> 1;
    int mrow = wy * 32;
    int ncol = wx * 64;

    int blk = blockIdx.x;
    int b   = blk >> 8;
    int rem = blk & 255;
    int i   = rem >> 1;
    int jh  = rem & 1;
    int j0  = jh * 64;

    // ---- prefetch chunk 0 ----
#pragma unroll
    for (int r = 0; r < 8; r++) {
        int idx = tid + r * 256;
        int o = idx >> 3, c4 = idx & 7;
        uint32_t inner = (uint32_t)((c4 * 16) ^ ((o & 3) << 5));
        cpa16(w_u32 + (uint32_t)o * 128 + inner, g_Wh + o * 64 + c4 * 8);
    }
    cpa_commit();

    // ---- build h1 while chunk 0 flies ----
    {
        int p   = tid & 127;
        int rg  = tid >> 7;
        int c0  = 2 * p;
        float a0 = g_A[(b * NI + i) * C2 + c0];
        float a1 = g_A[(b * NI + i) * C2 + c0 + 1];
        const float* bp0 = g_Bvt + (b * C2 + c0)     * NI + j0 + rg * 32;
        const float* bp1 = g_Bvt + (b * C2 + c0 + 1) * NI + j0 + rg * 32;
        int pcb = pg16(c0) * 2;
#pragma unroll
        for (int r4 = 0; r4 < 32; r4 += 4) {
            float4 v0 = *(const float4*)(bp0 + r4);
            float4 v1 = *(const float4*)(bp1 + r4);
            int row = rg * 32 + r4;
#pragma unroll
            for (int q = 0; q < 4; q++) {
                float e0 = (q == 0 ? v0.x : q == 1 ? v0.y : q == 2 ? v0.z : v0.w);
                float e1 = (q == 0 ? v1.x : q == 1 ? v1.y : q == 2 ? v1.z : v1.w);
                __half2 hv = __floats2half2_rn(fmaxf(e0 + a0, 0.f), fmaxf(e1 + a1, 0.f));
                int rr = row + q;
                *(__half2*)(hb + rr * 512 + (pcb ^ ((rr & 3) << 5))) = hv;
            }
        }
    }

    float acc[2][8][4];
#pragma unroll
    for (int mt = 0; mt < 2; mt++)
#pragma unroll
        for (int nt = 0; nt < 8; nt++)
#pragma unroll
            for (int q = 0; q < 4; q++) acc[mt][nt][q] = 0.f;

    for (int ck = 0; ck < NCHUNK; ck++) {
        cpa_wait0();
        __syncthreads();

        if (ck < NCHUNK - 1) {             // prefetch ck+1 into the other buffer
            const __half* src = g_Wh + (ck + 1) * 16384;
            uint32_t dbase = w_u32 + (uint32_t)(((ck + 1) & 1) * WBUF);
#pragma unroll
            for (int r = 0; r < 8; r++) {
                int idx = tid + r * 256;
                int o = idx >> 3, c4 = idx & 7;
                uint32_t inner = (uint32_t)((c4 * 16) ^ ((o & 3) << 5));
                cpa16(dbase + (uint32_t)o * 128 + inner, src + o * 64 + c4 * 8);
            }
            cpa_commit();
        }

        // ---- compute chunk ck (K=64 -> 4 ksteps of 16) ----
        char* wc  = wbase + (ck & 1) * WBUF;
        int   ckb = (ck & 3) * 128;
#pragma unroll
        for (int ks = 0; ks < 4; ks++) {
            uint32_t a[2][4];
#pragma unroll
            for (int mt = 0; mt < 2; mt++) {
                int r0 = mrow + mt * 16 + (lane >> 2);
                uint32_t inner = (uint32_t)((ckb + ks * 32 + (lane & 3) * 8));
                uint2 lo = *(const uint2*)(hb + r0 * 512 + (inner ^ ((r0 & 3) << 5)));
                int r8 = r0 + 8;
                uint2 hi = *(const uint2*)(hb + r8 * 512 + (inner ^ ((r8 & 3) << 5)));
                a[mt][0] = lo.x; a[mt][2] = lo.y;
                a[mt][1] = hi.x; a[mt][3] = hi.y;
            }
#pragma unroll
            for (int nt = 0; nt < 8; nt++) {
                int o = ncol + nt * 8 + (lane >> 2);
                uint32_t inner = (uint32_t)((ks * 32 + (lane & 3) * 8) ^ ((o & 3) << 5));
                uint2 bv = *(const uint2*)(wc + o * 128 + inner);
                uint32_t bfr[2] = {bv.x, bv.y};
                mma16(acc[0][nt], a[0], bfr);
                mma16(acc[1][nt], a[1], bfr);
            }
        }

        if (ck == 3) {
            // layer boundary: overwrite h with h2 (same permuted+swizzled layout)
            __syncthreads();
#pragma unroll
            for (int mt = 0; mt < 2; mt++) {
                int r = mrow + mt * 16 + (lane >> 2);
#pragma unroll
                for (int nt = 0; nt < 8; nt++) {
                    int c0 = ncol + nt * 8 + 2 * (lane & 3);
                    int pcb = pg16(c0) * 2;
                    __half2 v01 = __floats2half2_rn(fmaxf(acc[mt][nt][0], 0.f),
                                                    fmaxf(acc[mt][nt][1], 0.f));
                    __half2 v23 = __floats2half2_rn(fmaxf(acc[mt][nt][2], 0.f),
                                                    fmaxf(acc[mt][nt][3], 0.f));
                    int r8 = r + 8;
                    *(__half2*)(hb + r * 512 + (pcb ^ ((r & 3) << 5)))   = v01;
                    *(__half2*)(hb + r8 * 512 + (pcb ^ ((r8 & 3) << 5))) = v23;
#pragma unroll
                    for (int q = 0; q < 4; q++) acc[mt][nt][q] = 0.f;
                }
            }
        }
    }

    // ---- epilogue: relu + deterministic sum over the CTA's 64 rows ----
    __syncthreads();
    float* red = (float*)wbase;            // [2][256]
#pragma unroll
    for (int nt = 0; nt < 8; nt++) {
        float ev = 0.f, od = 0.f;
#pragma unroll
        for (int mt = 0; mt < 2; mt++) {
            ev += fmaxf(acc[mt][nt][0], 0.f) + fmaxf(acc[mt][nt][2], 0.f);
            od += fmaxf(acc[mt][nt][1], 0.f) + fmaxf(acc[mt][nt][3], 0.f);
        }
#pragma unroll
        for (int o = 4; o <= 16; o <<= 1) {
            ev += __shfl_xor_sync(0xffffffffu, ev, o);
            od += __shfl_xor_sync(0xffffffffu, od, o);
        }
        if (lane < 4) {
            red[wy * C2 + ncol + nt * 8 + 2 * lane]     = ev;
            red[wy * C2 + ncol + nt * 8 + 2 * lane + 1] = od;
        }
    }
    __syncthreads();
    g_part[((b * NI + i) * 2 + jh) * C2 + tid] = red[tid] + red[C2 + tid];
}

// ---------------------------------------------------------------------------
__global__ __launch_bounds__(512) void k_fin(float* __restrict__ out)
{
    int idx = blockIdx.x * 512 + threadIdx.x;
    int c = idx & 255, bn = idx >> 8;
    int b = bn >> 4, n1 = bn & 15;
    float sum = 0.f;
#pragma unroll
    for (int k1 = 0; k1 < 8; k1++)
#pragma unroll
        for (int jhv = 0; jhv < 2; jhv++)
            sum += g_part[((b * NI + n1 * 8 + k1) * 2 + jhv) * C2 + c];
    out[idx] = sum * (1.0f / 1024.0f);
}

// ---------------------------------------------------------------------------
extern "C" void kernel_launch(void* const* d_in, const int* in_sizes, int n_in,
                              void* d_out, int out_size)
{
    const float* enc = (const float*)d_in[0];
    const float* W1  = (const float*)d_in[1];
    const float* W2  = (const float*)d_in[2];
    const float* W3  = (const float*)d_in[3];
    float* out       = (float*)d_out;

    const int smem_main = HBUF + 2 * WBUF;   // 98304
    const int smem_abt  = 4096 + 512 * 256;  // 135168
    cudaFuncSetAttribute(k_main, cudaFuncAttributeMaxDynamicSharedMemorySize, smem_main);
    cudaFuncSetAttribute(k_abt,  cudaFuncAttributeMaxDynamicSharedMemorySize, smem_abt);

    k_prep<<<896, 256>>>(enc, W1, W2, W3);
    k_abt <<<BB * NI / 16, 256, smem_abt>>>();
    k_main<<<BB * NI * 2, 256, smem_main>>>();
    k_fin <<<(BB * NN * C2) / 512, 512>>>(out);
}